// round 1
// baseline (speedup 1.0000x reference)
#include <cuda_runtime.h>
#include <cstdint>
#include <math.h>

#define BATCH 64
#define SEQ   512
#define INSZ  512
#define HSZ   512
#define G4    2048   // 4*HSZ

// ---------------- scratch (device globals; no allocation allowed) ----------
__device__ float g_xproj[(size_t)BATCH * SEQ * G4];   // 256 MB: x @ W_ih, row = b*SEQ+t
__device__ float g_h[2][BATCH * HSZ];                 // ping-pong hidden state
__device__ float g_c[BATCH * HSZ];                    // cell state

// ---------------- f32x2 packed math helpers (sm_103a) ----------------------
__device__ __forceinline__ unsigned long long pack2(float lo, float hi) {
    unsigned long long r;
    asm("mov.b64 %0, {%1, %2};" : "=l"(r) : "f"(lo), "f"(hi));
    return r;
}
__device__ __forceinline__ void unpack2(unsigned long long v, float& lo, float& hi) {
    asm("mov.b64 {%0, %1}, %2;" : "=f"(lo), "=f"(hi) : "l"(v));
}
__device__ __forceinline__ unsigned long long ffma2(unsigned long long a,
                                                    unsigned long long b,
                                                    unsigned long long c) {
    unsigned long long d;
    asm("fma.rn.f32x2 %0, %1, %2, %3;" : "=l"(d) : "l"(a), "l"(b), "l"(c));
    return d;
}

__device__ __forceinline__ float sigmoidf_(float x) {
    return 1.0f / (1.0f + expf(-x));
}

// ---------------- init: load h0/c0 into state buffers ----------------------
__global__ void init_state(const float* __restrict__ h0, const float* __restrict__ c0) {
    int idx = blockIdx.x * blockDim.x + threadIdx.x;
    if (idx < BATCH * HSZ) {
        g_h[0][idx] = h0[idx];
        g_c[idx]    = c0[idx];
    }
}

// ---------------- kernel 1: x_proj = x @ W_ih ------------------------------
// M = BATCH*SEQ = 32768, N = G4 = 2048, K = INSZ = 512
// CTA tile 64x64, BK = 16, 256 threads, per-thread 4x4 via f32x2 pairs in N.
__global__ __launch_bounds__(256) void xproj_gemm(const float* __restrict__ X,
                                                  const float* __restrict__ Wih) {
    __shared__ float  As[16][64];    // [k][m]
    __shared__ float4 Bs[16][16];    // [k][n/4]

    const int tid = threadIdx.x;
    const int m0 = blockIdx.y * 64;
    const int n0 = blockIdx.x * 64;
    const int tx = tid % 16;          // N: 4 cols  (2 f32x2 pairs)
    const int ty = tid / 16;          // M: 4 rows

    unsigned long long acc[4][2];
#pragma unroll
    for (int i = 0; i < 4; i++) { acc[i][0] = 0ull; acc[i][1] = 0ull; }

    const int arow = tid / 4;         // 0..63
    const int acg  = (tid % 4) * 4;   // 0,4,8,12
    const int brow = tid / 16;        // 0..15
    const int bcg  = tid % 16;        // 0..15

    for (int k0 = 0; k0 < INSZ; k0 += 16) {
        float4 av = *(const float4*)&X[(size_t)(m0 + arow) * INSZ + k0 + acg];
        As[acg + 0][arow] = av.x;
        As[acg + 1][arow] = av.y;
        As[acg + 2][arow] = av.z;
        As[acg + 3][arow] = av.w;
        Bs[brow][bcg] = *(const float4*)&Wih[(size_t)(k0 + brow) * G4 + n0 + bcg * 4];
        __syncthreads();

        const unsigned long long* Bs2 = (const unsigned long long*)Bs;  // [16][32]
#pragma unroll
        for (int kk = 0; kk < 16; kk++) {
            unsigned long long b0 = Bs2[kk * 32 + tx * 2 + 0];
            unsigned long long b1 = Bs2[kk * 32 + tx * 2 + 1];
#pragma unroll
            for (int i = 0; i < 4; i++) {
                float a = As[kk][ty * 4 + i];
                unsigned long long pa = pack2(a, a);
                acc[i][0] = ffma2(pa, b0, acc[i][0]);
                acc[i][1] = ffma2(pa, b1, acc[i][1]);
            }
        }
        __syncthreads();
    }

#pragma unroll
    for (int i = 0; i < 4; i++) {
        float x0, x1, x2, x3;
        unpack2(acc[i][0], x0, x1);
        unpack2(acc[i][1], x2, x3);
        float4 v = make_float4(x0, x1, x2, x3);
        *(float4*)&g_xproj[(size_t)(m0 + ty * 4 + i) * G4 + n0 + tx * 4] = v;
    }
}

// ---------------- kernel 2: one LSTM timestep ------------------------------
// gates = x_proj[t] + h_{t-1} @ W_hh + bias; pointwise update; emit h.
// Grid: (32 j-tiles of 16 cols, 4 b-tiles of 16 batches), 256 threads.
// Thread owns one (b, j): 4 gate dots over K=512, f32x2-packed as (i,f),(g,o).
__global__ __launch_bounds__(256) void lstm_step(const float* __restrict__ Whh,
                                                 const float* __restrict__ bias,
                                                 float* __restrict__ out,
                                                 int t) {
    __shared__ float2 Wif[32 * 16];   // [k][jl] -> (W_i, W_f)
    __shared__ float2 Wgo[32 * 16];   // [k][jl] -> (W_g, W_o)
    __shared__ float  hs[16 * 32];    // [bl][k]

    const int tid = threadIdx.x;
    const int jl = tid % 16;
    const int bl = tid / 16;
    const int jt = blockIdx.x;        // 0..31
    const int bt = blockIdx.y;        // 0..3
    const int j = jt * 16 + jl;
    const int b = bt * 16 + bl;

    const int cur = t & 1;
    const int nxt = cur ^ 1;
    const float* __restrict__ hin = g_h[cur];

    unsigned long long acc_if = 0ull, acc_go = 0ull;

    for (int kc = 0; kc < HSZ; kc += 32) {
        // stage h tile: 16 batches x 32 k  (512 floats, 2 per thread)
#pragma unroll
        for (int u = 0; u < 2; u++) {
            int idx = tid + u * 256;
            int r = idx / 32, c = idx % 32;
            hs[r * 32 + c] = hin[(bt * 16 + r) * HSZ + kc + c];
        }
        // stage W tiles: 32 k x 16 cols per gate, interleaved as pairs
#pragma unroll
        for (int u = 0; u < 2; u++) {
            int idx = tid + u * 256;
            int k = idx / 16, jj = idx % 16;
            const float* wr = &Whh[(size_t)(kc + k) * G4 + jt * 16 + jj];
            Wif[k * 16 + jj] = make_float2(wr[0],        wr[HSZ]);
            Wgo[k * 16 + jj] = make_float2(wr[2 * HSZ],  wr[3 * HSZ]);
        }
        __syncthreads();

#pragma unroll
        for (int k = 0; k < 32; k++) {
            float h = hs[bl * 32 + k];
            unsigned long long ph = pack2(h, h);
            unsigned long long wif = *(const unsigned long long*)&Wif[k * 16 + jl];
            unsigned long long wgo = *(const unsigned long long*)&Wgo[k * 16 + jl];
            acc_if = ffma2(ph, wif, acc_if);
            acc_go = ffma2(ph, wgo, acc_go);
        }
        __syncthreads();
    }

    float si, sf, sg, so;
    unpack2(acc_if, si, sf);
    unpack2(acc_go, sg, so);

    const size_t row = (size_t)b * SEQ + t;
    const float* xp = &g_xproj[row * G4];
    float gi = si + xp[j]            + bias[j];
    float gf = sf + xp[j + HSZ]      + bias[j + HSZ];
    float gg = sg + xp[j + 2 * HSZ]  + bias[j + 2 * HSZ];
    float go = so + xp[j + 3 * HSZ]  + bias[j + 3 * HSZ];

    float iv = sigmoidf_(gi);
    float fv = sigmoidf_(gf);
    float gv = tanhf(gg);
    float ov = sigmoidf_(go);

    const int sidx = b * HSZ + j;
    float c = fv * g_c[sidx] + iv * gv;
    g_c[sidx] = c;
    float h = ov * tanhf(c);
    g_h[nxt][sidx] = h;

    // hidden_seq[b][t][j]
    out[((size_t)b * SEQ + t) * HSZ + j] = h;
    if (t == SEQ - 1) {
        // h_T (1,B,H) then c_T (1,B,H) after hidden_seq
        out[(size_t)BATCH * SEQ * HSZ + sidx] = h;
        out[(size_t)BATCH * SEQ * HSZ + BATCH * HSZ + sidx] = c;
    }
}

// ---------------- launch ----------------------------------------------------
extern "C" void kernel_launch(void* const* d_in, const int* in_sizes, int n_in,
                              void* d_out, int out_size) {
    const float* x    = (const float*)d_in[0];
    const float* wih  = (const float*)d_in[1];
    const float* whh  = (const float*)d_in[2];
    const float* bias = (const float*)d_in[3];
    const float* h0   = (const float*)d_in[4];
    const float* c0   = (const float*)d_in[5];
    float* out = (float*)d_out;

    init_state<<<64, 512>>>(h0, c0);
    xproj_gemm<<<dim3(32, 512), 256>>>(x, wih);
    for (int t = 0; t < SEQ; t++) {
        lstm_step<<<dim3(32, 4), 256>>>(whh, bias, out, t);
    }
}

// round 3
// speedup vs baseline: 2.5073x; 2.5073x over previous
#include <cuda_runtime.h>
#include <cstdint>
#include <math.h>

#define BATCH 64
#define SEQ   512
#define INSZ  512
#define HSZ   512
#define G4    2048   // 4*HSZ
#define NCTA  128

// ---------------- scratch (device globals; no allocation allowed) ----------
__device__ float g_xproj[(size_t)BATCH * SEQ * G4];   // 256 MB: x @ W_ih, row = b*SEQ+t
__device__ float g_hT[2][HSZ * BATCH];                // transposed hidden state: [j][b]
__device__ unsigned g_cnt;                            // monotonic grid-barrier counter

// ---------------- f32x2 packed math helpers (sm_103a) ----------------------
__device__ __forceinline__ unsigned long long pack2(float lo, float hi) {
    unsigned long long r;
    asm("mov.b64 %0, {%1, %2};" : "=l"(r) : "f"(lo), "f"(hi));
    return r;
}
__device__ __forceinline__ void unpack2(unsigned long long v, float& lo, float& hi) {
    asm("mov.b64 {%0, %1}, %2;" : "=f"(lo), "=f"(hi) : "l"(v));
}
__device__ __forceinline__ unsigned long long ffma2(unsigned long long a,
                                                    unsigned long long b,
                                                    unsigned long long c) {
    unsigned long long d;
    asm("fma.rn.f32x2 %0, %1, %2, %3;" : "=l"(d) : "l"(a), "l"(b), "l"(c));
    return d;
}
__device__ __forceinline__ float sigmoidf_(float x) {
    return 1.0f / (1.0f + expf(-x));
}

// ---------------- init: h0 -> transposed hidden buffer ---------------------
__global__ void init_state(const float* __restrict__ h0) {
    int idx = blockIdx.x * blockDim.x + threadIdx.x;
    if (idx < BATCH * HSZ) {
        int b = idx / HSZ, j = idx % HSZ;
        g_hT[0][j * BATCH + b] = h0[idx];
    }
}

// ---------------- kernel 1: x_proj = x @ W_ih ------------------------------
__global__ __launch_bounds__(256) void xproj_gemm(const float* __restrict__ X,
                                                  const float* __restrict__ Wih) {
    __shared__ float  As[16][64];    // [k][m]
    __shared__ float4 Bs[16][16];    // [k][n/4]

    const int tid = threadIdx.x;
    const int m0 = blockIdx.y * 64;
    const int n0 = blockIdx.x * 64;
    const int tx = tid % 16;
    const int ty = tid / 16;

    unsigned long long acc[4][2];
#pragma unroll
    for (int i = 0; i < 4; i++) { acc[i][0] = 0ull; acc[i][1] = 0ull; }

    const int arow = tid / 4;
    const int acg  = (tid % 4) * 4;
    const int brow = tid / 16;
    const int bcg  = tid % 16;

    for (int k0 = 0; k0 < INSZ; k0 += 16) {
        float4 av = *(const float4*)&X[(size_t)(m0 + arow) * INSZ + k0 + acg];
        As[acg + 0][arow] = av.x;
        As[acg + 1][arow] = av.y;
        As[acg + 2][arow] = av.z;
        As[acg + 3][arow] = av.w;
        Bs[brow][bcg] = *(const float4*)&Wih[(size_t)(k0 + brow) * G4 + n0 + bcg * 4];
        __syncthreads();

        const unsigned long long* Bs2 = (const unsigned long long*)Bs;
#pragma unroll
        for (int kk = 0; kk < 16; kk++) {
            unsigned long long b0 = Bs2[kk * 32 + tx * 2 + 0];
            unsigned long long b1 = Bs2[kk * 32 + tx * 2 + 1];
#pragma unroll
            for (int i = 0; i < 4; i++) {
                float a = As[kk][ty * 4 + i];
                unsigned long long pa = pack2(a, a);
                acc[i][0] = ffma2(pa, b0, acc[i][0]);
                acc[i][1] = ffma2(pa, b1, acc[i][1]);
            }
        }
        __syncthreads();
    }

#pragma unroll
    for (int i = 0; i < 4; i++) {
        float x0, x1, x2, x3;
        unpack2(acc[i][0], x0, x1);
        unpack2(acc[i][1], x2, x3);
        float4 v = make_float4(x0, x1, x2, x3);
        *(float4*)&g_xproj[(size_t)(m0 + ty * 4 + i) * G4 + n0 + tx * 4] = v;
    }
}

// ---------------- kernel 2: persistent LSTM recurrence ---------------------
// 128 CTAs (1/SM), W_hh slice resident in SMEM for all 512 steps.
// smem: W2 [512][32] f32x2 = 128KB; hsT [512][16] = 32KB; red [8][4][16][16] = 32KB.
__global__ __launch_bounds__(256, 1) void lstm_persist(
    const float* __restrict__ Whh, const float* __restrict__ bias,
    const float* __restrict__ c0,  float* __restrict__ out) {
    extern __shared__ float smem[];
    float2* W2  = (float2*)smem;          // [k][jl*2+gp] -> (Wi,Wf)/(Wg,Wo)
    float*  hsT = smem + 32768;           // [k][b]
    float*  red = smem + 32768 + 8192;    // [warp][gate][b][jl]  (8192 floats!)

    const int tid  = threadIdx.x;
    const int wid  = tid >> 5;
    const int lane = tid & 31;
    const int jt = blockIdx.x & 31, bt = blockIdx.x >> 5;
    const int j0 = jt * 16, b0 = bt * 16;

    // --- load W slice once: 512 k x 16 jl x 4 gates = 128KB ---
    for (int idx = tid; idx < 512 * 16; idx += 256) {
        int k = idx >> 4, jl = idx & 15;
        const float* wr = Whh + (size_t)k * G4 + j0 + jl;
        W2[k * 32 + jl * 2 + 0] = make_float2(wr[0],       wr[HSZ]);
        W2[k * 32 + jl * 2 + 1] = make_float2(wr[2 * HSZ], wr[3 * HSZ]);
    }

    // --- update-thread identity: one (b, j) output per thread ---
    const int bl = tid >> 4, jl_u = tid & 15;
    const int b = b0 + bl, j = j0 + jl_u;
    float cc = c0[(size_t)b * HSZ + j];
    const float bi = bias[j], bf = bias[j + HSZ];
    const float bg = bias[j + 2 * HSZ], bo = bias[j + 3 * HSZ];

    // --- compute identity: warp owns k-slice, lane owns (jl, gate-pair) ---
    const int ks0 = wid * 64;
    const int jl_c = lane >> 1, gp = lane & 1;
    float* rA = &red[((wid * 4 + gp * 2 + 0) * 16) * 16 + jl_c];
    float* rB = &red[((wid * 4 + gp * 2 + 1) * 16) * 16 + jl_c];

    for (int t = 0; t < SEQ; t++) {
        const int cur = t & 1;
        const float* hin = g_hT[cur];

        // stage h tile: [k][b] transposed layout, conflict-free, L2-coherent
#pragma unroll
        for (int it = 0; it < 8; it++) {
            int lin = tid + it * 256;            // float4 slot 0..2047
            int k = lin >> 2, b4 = (lin & 3) << 2;
            float4 v = __ldcg((const float4*)&hin[k * BATCH + b0 + b4]);
            *(float4*)&hsT[k * 16 + b4] = v;
        }
        // prefetch this step's x_proj contribution
        const float* xp = g_xproj + ((size_t)b * SEQ + t) * G4 + j;
        float xi = __ldg(xp);
        float xf = __ldg(xp + HSZ);
        float xg = __ldg(xp + 2 * HSZ);
        float xo = __ldg(xp + 3 * HSZ);
        __syncthreads();

        // --- GEMM slice: 16 f32x2 accumulators packed over batch pairs ---
        unsigned long long accA[8], accB[8];
#pragma unroll
        for (int p = 0; p < 8; p++) { accA[p] = 0ull; accB[p] = 0ull; }

#pragma unroll 4
        for (int k = ks0; k < ks0 + 64; k++) {
            float2 w = W2[k * 32 + lane];
            unsigned long long wa = pack2(w.x, w.x);
            unsigned long long wb = pack2(w.y, w.y);
            const ulonglong2* hp = (const ulonglong2*)&hsT[k * 16];
            ulonglong2 h01 = hp[0], h23 = hp[1], h45 = hp[2], h67 = hp[3];
            accA[0] = ffma2(h01.x, wa, accA[0]); accB[0] = ffma2(h01.x, wb, accB[0]);
            accA[1] = ffma2(h01.y, wa, accA[1]); accB[1] = ffma2(h01.y, wb, accB[1]);
            accA[2] = ffma2(h23.x, wa, accA[2]); accB[2] = ffma2(h23.x, wb, accB[2]);
            accA[3] = ffma2(h23.y, wa, accA[3]); accB[3] = ffma2(h23.y, wb, accB[3]);
            accA[4] = ffma2(h45.x, wa, accA[4]); accB[4] = ffma2(h45.x, wb, accB[4]);
            accA[5] = ffma2(h45.y, wa, accA[5]); accB[5] = ffma2(h45.y, wb, accB[5]);
            accA[6] = ffma2(h67.x, wa, accA[6]); accB[6] = ffma2(h67.x, wb, accB[6]);
            accA[7] = ffma2(h67.y, wa, accA[7]); accB[7] = ffma2(h67.y, wb, accB[7]);
        }

        // --- write split-K partials ---
#pragma unroll
        for (int p = 0; p < 8; p++) {
            float lo, hi;
            unpack2(accA[p], lo, hi);
            rA[(2 * p) * 16] = lo; rA[(2 * p + 1) * 16] = hi;
            unpack2(accB[p], lo, hi);
            rB[(2 * p) * 16] = lo; rB[(2 * p + 1) * 16] = hi;
        }
        __syncthreads();

        // --- reduce 8 warps + pointwise LSTM cell ---
        float si = 0.f, sf = 0.f, sg = 0.f, so = 0.f;
#pragma unroll
        for (int w = 0; w < 8; w++) {
            const float* rp = &red[((w * 4) * 16 + bl) * 16 + jl_u];
            si += rp[0];
            sf += rp[256];
            sg += rp[512];
            so += rp[768];
        }
        float gi = si + xi + bi, gf = sf + xf + bf;
        float gg = sg + xg + bg, go = so + xo + bo;
        float iv = sigmoidf_(gi), fv = sigmoidf_(gf);
        float gv = tanhf(gg),    ov = sigmoidf_(go);
        cc = fv * cc + iv * gv;
        float hv = ov * tanhf(cc);

        out[((size_t)b * SEQ + t) * HSZ + j] = hv;
        __stcg(&g_hT[cur ^ 1][j * BATCH + b], hv);
        if (t == SEQ - 1) {
            out[(size_t)BATCH * SEQ * HSZ + (size_t)b * HSZ + j] = hv;
            out[(size_t)BATCH * SEQ * HSZ + BATCH * HSZ + (size_t)b * HSZ + j] = cc;
        }

        // --- grid barrier (monotonic counter: graph-replay safe) ---
        __syncthreads();
        if (tid == 0) {
            __threadfence();
            unsigned tk = atomicAdd(&g_cnt, 1u) + 1u;
            unsigned target = (tk + (NCTA - 1)) & ~(unsigned)(NCTA - 1);
            while (*((volatile unsigned*)&g_cnt) < target) { }
            __threadfence();
        }
        __syncthreads();
    }
}

// ---------------- launch ----------------------------------------------------
extern "C" void kernel_launch(void* const* d_in, const int* in_sizes, int n_in,
                              void* d_out, int out_size) {
    const float* x    = (const float*)d_in[0];
    const float* wih  = (const float*)d_in[1];
    const float* whh  = (const float*)d_in[2];
    const float* bias = (const float*)d_in[3];
    const float* h0   = (const float*)d_in[4];
    const float* c0   = (const float*)d_in[5];
    float* out = (float*)d_out;

    const int smem_bytes = 131072 + 32768 + 32768;   // 196608 = 192KB
    cudaFuncSetAttribute(lstm_persist, cudaFuncAttributeMaxDynamicSharedMemorySize,
                         smem_bytes);

    init_state<<<64, 512>>>(h0);
    xproj_gemm<<<dim3(32, 512), 256>>>(x, wih);
    lstm_persist<<<NCTA, 256, smem_bytes>>>(whh, bias, c0, out);
}

// round 4
// speedup vs baseline: 2.5213x; 1.0056x over previous
#include <cuda_runtime.h>
#include <cstdint>
#include <math.h>

#define BATCH 64
#define SEQ   512
#define INSZ  512
#define HSZ   512
#define G4    2048   // 4*HSZ
#define NCTA  128
#define GRP   32     // CTAs per bt-group barrier

// ---------------- scratch (device globals; no allocation allowed) ----------
__device__ float g_xproj[(size_t)BATCH * SEQ * G4];   // 256 MB: x @ W_ih, row = b*SEQ+t
__device__ float g_hT[2][HSZ * BATCH];                // transposed hidden state: [j][b]
__device__ unsigned g_cnt4[4][32];                    // 4 group counters, 128B apart

// ---------------- f32x2 packed math helpers (sm_103a) ----------------------
__device__ __forceinline__ unsigned long long pack2(float lo, float hi) {
    unsigned long long r;
    asm("mov.b64 %0, {%1, %2};" : "=l"(r) : "f"(lo), "f"(hi));
    return r;
}
__device__ __forceinline__ void unpack2(unsigned long long v, float& lo, float& hi) {
    asm("mov.b64 {%0, %1}, %2;" : "=f"(lo), "=f"(hi) : "l"(v));
}
__device__ __forceinline__ unsigned long long ffma2(unsigned long long a,
                                                    unsigned long long b,
                                                    unsigned long long c) {
    unsigned long long d;
    asm("fma.rn.f32x2 %0, %1, %2, %3;" : "=l"(d) : "l"(a), "l"(b), "l"(c));
    return d;
}
__device__ __forceinline__ float sigmoidf_(float x) {
    return 1.0f / (1.0f + expf(-x));
}

// ---------------- init: h0 -> transposed hidden buffer ---------------------
__global__ void init_state(const float* __restrict__ h0) {
    int idx = blockIdx.x * blockDim.x + threadIdx.x;
    if (idx < BATCH * HSZ) {
        int b = idx / HSZ, j = idx % HSZ;
        g_hT[0][j * BATCH + b] = h0[idx];
    }
}

// ---------------- kernel 1: x_proj = x @ W_ih ------------------------------
__global__ __launch_bounds__(256) void xproj_gemm(const float* __restrict__ X,
                                                  const float* __restrict__ Wih) {
    __shared__ float  As[16][64];    // [k][m]
    __shared__ float4 Bs[16][16];    // [k][n/4]

    const int tid = threadIdx.x;
    const int m0 = blockIdx.y * 64;
    const int n0 = blockIdx.x * 64;
    const int tx = tid % 16;
    const int ty = tid / 16;

    unsigned long long acc[4][2];
#pragma unroll
    for (int i = 0; i < 4; i++) { acc[i][0] = 0ull; acc[i][1] = 0ull; }

    const int arow = tid / 4;
    const int acg  = (tid % 4) * 4;
    const int brow = tid / 16;
    const int bcg  = tid % 16;

    for (int k0 = 0; k0 < INSZ; k0 += 16) {
        float4 av = *(const float4*)&X[(size_t)(m0 + arow) * INSZ + k0 + acg];
        As[acg + 0][arow] = av.x;
        As[acg + 1][arow] = av.y;
        As[acg + 2][arow] = av.z;
        As[acg + 3][arow] = av.w;
        Bs[brow][bcg] = *(const float4*)&Wih[(size_t)(k0 + brow) * G4 + n0 + bcg * 4];
        __syncthreads();

        const unsigned long long* Bs2 = (const unsigned long long*)Bs;
#pragma unroll
        for (int kk = 0; kk < 16; kk++) {
            unsigned long long b0 = Bs2[kk * 32 + tx * 2 + 0];
            unsigned long long b1 = Bs2[kk * 32 + tx * 2 + 1];
#pragma unroll
            for (int i = 0; i < 4; i++) {
                float a = As[kk][ty * 4 + i];
                unsigned long long pa = pack2(a, a);
                acc[i][0] = ffma2(pa, b0, acc[i][0]);
                acc[i][1] = ffma2(pa, b1, acc[i][1]);
            }
        }
        __syncthreads();
    }

#pragma unroll
    for (int i = 0; i < 4; i++) {
        float x0, x1, x2, x3;
        unpack2(acc[i][0], x0, x1);
        unpack2(acc[i][1], x2, x3);
        float4 v = make_float4(x0, x1, x2, x3);
        *(float4*)&g_xproj[(size_t)(m0 + ty * 4 + i) * G4 + n0 + tx * 4] = v;
    }
}

// ---------------- kernel 2: persistent LSTM recurrence ---------------------
// 128 CTAs (1/SM), W_hh slice resident in SMEM for all 512 steps.
// smem: W2 [512][32] f32x2 = 128KB; hsT [512][16] = 32KB; red [8][4][16][16] = 32KB.
// Sync: 4 INDEPENDENT group barriers (one per bt batch-group of 32 CTAs) —
// h is only exchanged within a bt group, so no global barrier is needed.
__global__ __launch_bounds__(256, 1) void lstm_persist(
    const float* __restrict__ Whh, const float* __restrict__ bias,
    const float* __restrict__ c0,  float* __restrict__ out) {
    extern __shared__ float smem[];
    float2* W2  = (float2*)smem;          // [k][jl*2+gp] -> (Wi,Wf)/(Wg,Wo)
    float*  hsT = smem + 32768;           // [k][b]
    float*  red = smem + 32768 + 8192;    // [warp][gate][b][jl]

    const int tid  = threadIdx.x;
    const int wid  = tid >> 5;
    const int lane = tid & 31;
    const int jt = blockIdx.x & 31, bt = blockIdx.x >> 5;
    const int j0 = jt * 16, b0 = bt * 16;
    unsigned* cnt = &g_cnt4[bt][0];

    // --- load W slice once: 512 k x 16 jl x 4 gates = 128KB ---
    for (int idx = tid; idx < 512 * 16; idx += 256) {
        int k = idx >> 4, jl = idx & 15;
        const float* wr = Whh + (size_t)k * G4 + j0 + jl;
        W2[k * 32 + jl * 2 + 0] = make_float2(wr[0],       wr[HSZ]);
        W2[k * 32 + jl * 2 + 1] = make_float2(wr[2 * HSZ], wr[3 * HSZ]);
    }

    // --- update-thread identity: one (b, j) output per thread ---
    const int bl = tid >> 4, jl_u = tid & 15;
    const int b = b0 + bl, j = j0 + jl_u;
    float cc = c0[(size_t)b * HSZ + j];
    const float bi = bias[j], bf = bias[j + HSZ];
    const float bg = bias[j + 2 * HSZ], bo = bias[j + 3 * HSZ];

    // --- compute identity: warp owns k-slice, lane owns (jl, gate-pair) ---
    const int ks0 = wid * 64;
    const int jl_c = lane >> 1, gp = lane & 1;
    float* rA = &red[((wid * 4 + gp * 2 + 0) * 16) * 16 + jl_c];
    float* rB = &red[((wid * 4 + gp * 2 + 1) * 16) * 16 + jl_c];

    for (int t = 0; t < SEQ; t++) {
        const int cur = t & 1;
        const float* hin = g_hT[cur];

        // stage h tile: [k][b] transposed layout, conflict-free, L2-coherent
#pragma unroll
        for (int it = 0; it < 8; it++) {
            int lin = tid + it * 256;            // float4 slot 0..2047
            int k = lin >> 2, b4 = (lin & 3) << 2;
            float4 v = __ldcg((const float4*)&hin[k * BATCH + b0 + b4]);
            *(float4*)&hsT[k * 16 + b4] = v;
        }
        // prefetch this step's x_proj contribution (completes under the gemm)
        const float* xp = g_xproj + ((size_t)b * SEQ + t) * G4 + j;
        float xi = __ldg(xp);
        float xf = __ldg(xp + HSZ);
        float xg = __ldg(xp + 2 * HSZ);
        float xo = __ldg(xp + 3 * HSZ);
        __syncthreads();

        // --- GEMM slice: 16 f32x2 accumulators packed over batch pairs ---
        unsigned long long accA[8], accB[8];
#pragma unroll
        for (int p = 0; p < 8; p++) { accA[p] = 0ull; accB[p] = 0ull; }

#pragma unroll 4
        for (int k = ks0; k < ks0 + 64; k++) {
            float2 w = W2[k * 32 + lane];
            unsigned long long wa = pack2(w.x, w.x);
            unsigned long long wb = pack2(w.y, w.y);
            const ulonglong2* hp = (const ulonglong2*)&hsT[k * 16];
            ulonglong2 h01 = hp[0], h23 = hp[1], h45 = hp[2], h67 = hp[3];
            accA[0] = ffma2(h01.x, wa, accA[0]); accB[0] = ffma2(h01.x, wb, accB[0]);
            accA[1] = ffma2(h01.y, wa, accA[1]); accB[1] = ffma2(h01.y, wb, accB[1]);
            accA[2] = ffma2(h23.x, wa, accA[2]); accB[2] = ffma2(h23.x, wb, accB[2]);
            accA[3] = ffma2(h23.y, wa, accA[3]); accB[3] = ffma2(h23.y, wb, accB[3]);
            accA[4] = ffma2(h45.x, wa, accA[4]); accB[4] = ffma2(h45.x, wb, accB[4]);
            accA[5] = ffma2(h45.y, wa, accA[5]); accB[5] = ffma2(h45.y, wb, accB[5]);
            accA[6] = ffma2(h67.x, wa, accA[6]); accB[6] = ffma2(h67.x, wb, accB[6]);
            accA[7] = ffma2(h67.y, wa, accA[7]); accB[7] = ffma2(h67.y, wb, accB[7]);
        }

        // --- write split-K partials ---
#pragma unroll
        for (int p = 0; p < 8; p++) {
            float lo, hi;
            unpack2(accA[p], lo, hi);
            rA[(2 * p) * 16] = lo; rA[(2 * p + 1) * 16] = hi;
            unpack2(accB[p], lo, hi);
            rB[(2 * p) * 16] = lo; rB[(2 * p + 1) * 16] = hi;
        }
        __syncthreads();

        // --- reduce 8 warps + pointwise LSTM cell ---
        float si = 0.f, sf = 0.f, sg = 0.f, so = 0.f;
#pragma unroll
        for (int w = 0; w < 8; w++) {
            const float* rp = &red[((w * 4) * 16 + bl) * 16 + jl_u];
            si += rp[0];
            sf += rp[256];
            sg += rp[512];
            so += rp[768];
        }
        float gi = si + xi + bi, gf = sf + xf + bf;
        float gg = sg + xg + bg, go = so + xo + bo;
        float iv = sigmoidf_(gi), fv = sigmoidf_(gf);
        float gv = tanhf(gg),    ov = sigmoidf_(go);
        cc = fv * cc + iv * gv;
        float hv = ov * tanhf(cc);

        out[((size_t)b * SEQ + t) * HSZ + j] = hv;
        __stcg(&g_hT[cur ^ 1][j * BATCH + b], hv);
        if (t == SEQ - 1) {
            out[(size_t)BATCH * SEQ * HSZ + (size_t)b * HSZ + j] = hv;
            out[(size_t)BATCH * SEQ * HSZ + BATCH * HSZ + (size_t)b * HSZ + j] = cc;
        }

        // --- per-bt-group barrier (32 arrivals, monotonic: replay-safe) ---
        __syncthreads();
        if (tid == 0) {
            __threadfence();
            unsigned tk = atomicAdd(cnt, 1u) + 1u;
            unsigned target = (tk + (GRP - 1)) & ~(unsigned)(GRP - 1);
            while (*((volatile unsigned*)cnt) < target) { }
            __threadfence();
        }
        __syncthreads();
    }
}

// ---------------- launch ----------------------------------------------------
extern "C" void kernel_launch(void* const* d_in, const int* in_sizes, int n_in,
                              void* d_out, int out_size) {
    const float* x    = (const float*)d_in[0];
    const float* wih  = (const float*)d_in[1];
    const float* whh  = (const float*)d_in[2];
    const float* bias = (const float*)d_in[3];
    const float* h0   = (const float*)d_in[4];
    const float* c0   = (const float*)d_in[5];
    float* out = (float*)d_out;

    const int smem_bytes = 131072 + 32768 + 32768;   // 192KB
    cudaFuncSetAttribute(lstm_persist, cudaFuncAttributeMaxDynamicSharedMemorySize,
                         smem_bytes);

    init_state<<<64, 512>>>(h0);
    xproj_gemm<<<dim3(32, 512), 256>>>(x, wih);
    lstm_persist<<<NCTA, 256, smem_bytes>>>(whh, bias, c0, out);
}

// round 5
// speedup vs baseline: 2.5484x; 1.0108x over previous
#include <cuda_runtime.h>
#include <cstdint>
#include <math.h>

#define BATCH 64
#define SEQ   512
#define INSZ  512
#define HSZ   512
#define G4    2048   // 4*HSZ
#define NCTA  128
#define GRP   32     // CTAs per bt-group barrier

// ---------------- scratch (device globals; no allocation allowed) ----------
__device__ float g_xproj[(size_t)BATCH * SEQ * G4];   // 256 MB: x @ W_ih, row = b*SEQ+t
__device__ float g_hT[2][HSZ * BATCH];                // transposed hidden state: [j][b]
__device__ unsigned g_cnt4[4][32];                    // 4 group counters, 128B apart

// ---------------- f32x2 packed math helpers (sm_103a) ----------------------
__device__ __forceinline__ unsigned long long pack2(float lo, float hi) {
    unsigned long long r;
    asm("mov.b64 %0, {%1, %2};" : "=l"(r) : "f"(lo), "f"(hi));
    return r;
}
__device__ __forceinline__ void unpack2(unsigned long long v, float& lo, float& hi) {
    asm("mov.b64 {%0, %1}, %2;" : "=f"(lo), "=f"(hi) : "l"(v));
}
__device__ __forceinline__ unsigned long long ffma2(unsigned long long a,
                                                    unsigned long long b,
                                                    unsigned long long c) {
    unsigned long long d;
    asm("fma.rn.f32x2 %0, %1, %2, %3;" : "=l"(d) : "l"(a), "l"(b), "l"(c));
    return d;
}

// ---------------- fast activations (MUFU-based, rel err ~1e-6) -------------
__device__ __forceinline__ float ex2f(float x) {
    float y; asm("ex2.approx.f32 %0, %1;" : "=f"(y) : "f"(x)); return y;
}
__device__ __forceinline__ float rcpf(float x) {
    float y; asm("rcp.approx.f32 %0, %1;" : "=f"(y) : "f"(x)); return y;
}
#define LOG2E 1.4426950408889634f
__device__ __forceinline__ float fast_sigmoid(float x) {
    // 1/(1+e^-x); x<<0 -> ex2(+big)=inf -> rcp=0 OK; x>>0 -> ex2(-big)=0 -> 1 OK
    return rcpf(1.0f + ex2f(-x * LOG2E));
}
__device__ __forceinline__ float fast_tanh(float x) {
    float a = fabsf(x);
    float t = ex2f(-2.0f * LOG2E * a);         // e^{-2|x|} in (0,1]
    float r = 1.0f - 2.0f * t * rcpf(1.0f + t);
    return copysignf(r, x);
}

// ---------------- kernel 1: x_proj = x @ W_ih ------------------------------
__global__ __launch_bounds__(256) void xproj_gemm(const float* __restrict__ X,
                                                  const float* __restrict__ Wih) {
    __shared__ float  As[16][64];    // [k][m]
    __shared__ float4 Bs[16][16];    // [k][n/4]

    const int tid = threadIdx.x;
    const int m0 = blockIdx.y * 64;
    const int n0 = blockIdx.x * 64;
    const int tx = tid % 16;
    const int ty = tid / 16;

    unsigned long long acc[4][2];
#pragma unroll
    for (int i = 0; i < 4; i++) { acc[i][0] = 0ull; acc[i][1] = 0ull; }

    const int arow = tid / 4;
    const int acg  = (tid % 4) * 4;
    const int brow = tid / 16;
    const int bcg  = tid % 16;

    for (int k0 = 0; k0 < INSZ; k0 += 16) {
        float4 av = *(const float4*)&X[(size_t)(m0 + arow) * INSZ + k0 + acg];
        As[acg + 0][arow] = av.x;
        As[acg + 1][arow] = av.y;
        As[acg + 2][arow] = av.z;
        As[acg + 3][arow] = av.w;
        Bs[brow][bcg] = *(const float4*)&Wih[(size_t)(k0 + brow) * G4 + n0 + bcg * 4];
        __syncthreads();

        const unsigned long long* Bs2 = (const unsigned long long*)Bs;
#pragma unroll
        for (int kk = 0; kk < 16; kk++) {
            unsigned long long b0 = Bs2[kk * 32 + tx * 2 + 0];
            unsigned long long b1 = Bs2[kk * 32 + tx * 2 + 1];
#pragma unroll
            for (int i = 0; i < 4; i++) {
                float a = As[kk][ty * 4 + i];
                unsigned long long pa = pack2(a, a);
                acc[i][0] = ffma2(pa, b0, acc[i][0]);
                acc[i][1] = ffma2(pa, b1, acc[i][1]);
            }
        }
        __syncthreads();
    }

#pragma unroll
    for (int i = 0; i < 4; i++) {
        float x0, x1, x2, x3;
        unpack2(acc[i][0], x0, x1);
        unpack2(acc[i][1], x2, x3);
        float4 v = make_float4(x0, x1, x2, x3);
        *(float4*)&g_xproj[(size_t)(m0 + ty * 4 + i) * G4 + n0 + tx * 4] = v;
    }
}

// ---------------- kernel 2: persistent LSTM recurrence ---------------------
// 128 CTAs (1/SM). Prologue: init transposed h state (folded former init_state)
// + load W_hh slice to SMEM. Then 512 steps with per-bt-group barriers.
__global__ __launch_bounds__(256, 1) void lstm_persist(
    const float* __restrict__ Whh, const float* __restrict__ bias,
    const float* __restrict__ h0,  const float* __restrict__ c0,
    float* __restrict__ out) {
    extern __shared__ float smem[];
    float2* W2  = (float2*)smem;          // [k][jl*2+gp] -> (Wi,Wf)/(Wg,Wo) 128KB
    float*  hsT = smem + 32768;           // [k][b]                            32KB
    float*  red = smem + 32768 + 8192;    // [warp][gate][b][jl]               32KB

    const int tid  = threadIdx.x;
    const int wid  = tid >> 5;
    const int lane = tid & 31;
    const int jt = blockIdx.x & 31, bt = blockIdx.x >> 5;
    const int j0 = jt * 16, b0 = bt * 16;
    unsigned* cnt = &g_cnt4[bt][0];

    // --- update-thread identity: one (b, j) output per thread ---
    const int bl = tid >> 4, jl_u = tid & 15;
    const int b = b0 + bl, j = j0 + jl_u;

    // --- init h state slice (replaces init_state kernel) ---
    __stcg(&g_hT[0][j * BATCH + b], h0[(size_t)b * HSZ + j]);

    // --- load W slice once: 512 k x 16 jl x 4 gates = 128KB ---
    for (int idx = tid; idx < 512 * 16; idx += 256) {
        int k = idx >> 4, jl = idx & 15;
        const float* wr = Whh + (size_t)k * G4 + j0 + jl;
        W2[k * 32 + jl * 2 + 0] = make_float2(wr[0],       wr[HSZ]);
        W2[k * 32 + jl * 2 + 1] = make_float2(wr[2 * HSZ], wr[3 * HSZ]);
    }

    float cc = c0[(size_t)b * HSZ + j];
    const float bi = bias[j], bf = bias[j + HSZ];
    const float bg = bias[j + 2 * HSZ], bo = bias[j + 3 * HSZ];

    // --- compute identity: warp owns k-slice, lane owns (jl, gate-pair) ---
    const int ks0 = wid * 64;
    const int jl_c = lane >> 1, gp = lane & 1;
    float* rA = &red[((wid * 4 + gp * 2 + 0) * 16) * 16 + jl_c];
    float* rB = &red[((wid * 4 + gp * 2 + 1) * 16) * 16 + jl_c];

    // --- group barrier after init writes (monotonic counter: replay-safe) ---
    __syncthreads();
    if (tid == 0) {
        __threadfence();
        unsigned tk = atomicAdd(cnt, 1u) + 1u;
        unsigned target = (tk + (GRP - 1)) & ~(unsigned)(GRP - 1);
        while (*((volatile unsigned*)cnt) < target) { }
        __threadfence();
    }
    __syncthreads();

    for (int t = 0; t < SEQ; t++) {
        const int cur = t & 1;
        const float* hin = g_hT[cur];

        // prefetch this step's x_proj contribution (DRAM; consumed post-gemm)
        const float* xp = g_xproj + ((size_t)b * SEQ + t) * G4 + j;
        float xi = __ldg(xp);
        float xf = __ldg(xp + HSZ);
        float xg = __ldg(xp + 2 * HSZ);
        float xo = __ldg(xp + 3 * HSZ);

        // stage h tile: [k][b] transposed layout, conflict-free, L2-coherent
#pragma unroll
        for (int it = 0; it < 8; it++) {
            int lin = tid + it * 256;            // float4 slot 0..2047
            int k = lin >> 2, b4 = (lin & 3) << 2;
            float4 v = __ldcg((const float4*)&hin[k * BATCH + b0 + b4]);
            *(float4*)&hsT[k * 16 + b4] = v;
        }
        __syncthreads();

        // --- GEMM slice: 16 f32x2 accumulators packed over batch pairs ---
        unsigned long long accA[8], accB[8];
#pragma unroll
        for (int p = 0; p < 8; p++) { accA[p] = 0ull; accB[p] = 0ull; }

#pragma unroll 4
        for (int k = ks0; k < ks0 + 64; k++) {
            float2 w = W2[k * 32 + lane];
            unsigned long long wa = pack2(w.x, w.x);
            unsigned long long wb = pack2(w.y, w.y);
            const ulonglong2* hp = (const ulonglong2*)&hsT[k * 16];
            ulonglong2 h01 = hp[0], h23 = hp[1], h45 = hp[2], h67 = hp[3];
            accA[0] = ffma2(h01.x, wa, accA[0]); accB[0] = ffma2(h01.x, wb, accB[0]);
            accA[1] = ffma2(h01.y, wa, accA[1]); accB[1] = ffma2(h01.y, wb, accB[1]);
            accA[2] = ffma2(h23.x, wa, accA[2]); accB[2] = ffma2(h23.x, wb, accB[2]);
            accA[3] = ffma2(h23.y, wa, accA[3]); accB[3] = ffma2(h23.y, wb, accB[3]);
            accA[4] = ffma2(h45.x, wa, accA[4]); accB[4] = ffma2(h45.x, wb, accB[4]);
            accA[5] = ffma2(h45.y, wa, accA[5]); accB[5] = ffma2(h45.y, wb, accB[5]);
            accA[6] = ffma2(h67.x, wa, accA[6]); accB[6] = ffma2(h67.x, wb, accB[6]);
            accA[7] = ffma2(h67.y, wa, accA[7]); accB[7] = ffma2(h67.y, wb, accB[7]);
        }

        // --- write split-K partials ---
#pragma unroll
        for (int p = 0; p < 8; p++) {
            float lo, hi;
            unpack2(accA[p], lo, hi);
            rA[(2 * p) * 16] = lo; rA[(2 * p + 1) * 16] = hi;
            unpack2(accB[p], lo, hi);
            rB[(2 * p) * 16] = lo; rB[(2 * p + 1) * 16] = hi;
        }
        __syncthreads();

        // --- reduce 8 warps + pointwise LSTM cell (fast activations) ---
        float si = 0.f, sf = 0.f, sg = 0.f, so = 0.f;
#pragma unroll
        for (int w = 0; w < 8; w++) {
            const float* rp = &red[((w * 4) * 16 + bl) * 16 + jl_u];
            si += rp[0];
            sf += rp[256];
            sg += rp[512];
            so += rp[768];
        }
        float gi = si + xi + bi, gf = sf + xf + bf;
        float gg = sg + xg + bg, go = so + xo + bo;
        float iv = fast_sigmoid(gi), fv = fast_sigmoid(gf);
        float gv = fast_tanh(gg),    ov = fast_sigmoid(go);
        cc = fv * cc + iv * gv;
        float hv = ov * fast_tanh(cc);

        // cross-CTA-visible store first
        __stcg(&g_hT[cur ^ 1][j * BATCH + b], hv);
        out[((size_t)b * SEQ + t) * HSZ + j] = hv;
        if (t == SEQ - 1) {
            out[(size_t)BATCH * SEQ * HSZ + (size_t)b * HSZ + j] = hv;
            out[(size_t)BATCH * SEQ * HSZ + BATCH * HSZ + (size_t)b * HSZ + j] = cc;
        }

        // --- per-bt-group barrier (32 arrivals, monotonic: replay-safe) ---
        __syncthreads();
        if (tid == 0) {
            __threadfence();
            unsigned tk = atomicAdd(cnt, 1u) + 1u;
            unsigned target = (tk + (GRP - 1)) & ~(unsigned)(GRP - 1);
            while (*((volatile unsigned*)cnt) < target) { }
            __threadfence();
        }
        __syncthreads();
    }
}

// ---------------- launch ----------------------------------------------------
extern "C" void kernel_launch(void* const* d_in, const int* in_sizes, int n_in,
                              void* d_out, int out_size) {
    const float* x    = (const float*)d_in[0];
    const float* wih  = (const float*)d_in[1];
    const float* whh  = (const float*)d_in[2];
    const float* bias = (const float*)d_in[3];
    const float* h0   = (const float*)d_in[4];
    const float* c0   = (const float*)d_in[5];
    float* out = (float*)d_out;

    const int smem_bytes = 131072 + 32768 + 32768;   // 192KB
    cudaFuncSetAttribute(lstm_persist, cudaFuncAttributeMaxDynamicSharedMemorySize,
                         smem_bytes);

    xproj_gemm<<<dim3(32, 512), 256>>>(x, wih);
    lstm_persist<<<NCTA, 256, smem_bytes>>>(whh, bias, h0, c0, out);
}